// round 3
// baseline (speedup 1.0000x reference)
#include <cuda_runtime.h>

#define NN 100000
#define NE 1200000
#define D  64

// Scratch (device globals — no allocation allowed)
__device__ float g_dis[NN];        // degree, then rsqrt(degree)
__device__ float g_h[NN * D];      // h = x @ W^T
__device__ float g_norm[NE];       // per-edge norm coefficient

// ---------------------------------------------------------------------------
__global__ void k_init_deg() {
    int i = blockIdx.x * blockDim.x + threadIdx.x;
    if (i < NN) g_dis[i] = 1.0f;   // self-loop weight
}

__global__ void k_deg(const int* __restrict__ dst, const float* __restrict__ ew) {
    int e = blockIdx.x * blockDim.x + threadIdx.x;
    if (e < NE) atomicAdd(&g_dis[dst[e]], ew[e]);
}

__global__ void k_rsqrt() {
    int i = blockIdx.x * blockDim.x + threadIdx.x;
    if (i < NN) g_dis[i] = rsqrtf(g_dis[i]);
}

// norm[e] = dis[src]*ew*dis[dst]
__global__ void k_norm(const int* __restrict__ src, const int* __restrict__ dst,
                       const float* __restrict__ ew) {
    int e = blockIdx.x * blockDim.x + threadIdx.x;
    if (e < NE) g_norm[e] = g_dis[src[e]] * ew[e] * g_dis[dst[e]];
}

// ---------------------------------------------------------------------------
// GEMM h = x @ W^T fused with self-loop term (out = dis^2 * h).
// 256 threads, 96 rows/block. Thread (cg,rg): cols [8cg,8cg+8), rows rg+{0,32,64}.
// k-loop chunked by 4: X via LDS.128 (stride-68 rows -> conflict-free).
#define GROWS 96
#define XSTRIDE 68
__global__ __launch_bounds__(256) void k_gemm(const float* __restrict__ x,
                                              const float* __restrict__ W,
                                              float* __restrict__ out) {
    __shared__ float Wt[D * D];            // Wt[k*64 + j] = W[j][k]
    __shared__ float Xs[GROWS * XSTRIDE];

    for (int t = threadIdx.x; t < D * D; t += 256) {
        int j = t >> 6, k = t & 63;
        Wt[k * D + j] = W[t];
    }

    const int base = blockIdx.x * GROWS;

    for (int t = threadIdx.x; t < GROWS * 16; t += 256) {
        int r = t >> 4, c4 = (t & 15) << 2;
        int gi = base + r;
        float4 v = make_float4(0.f, 0.f, 0.f, 0.f);
        if (gi < NN) v = *(const float4*)&x[gi * D + c4];
        *(float4*)&Xs[r * XSTRIDE + c4] = v;
    }
    __syncthreads();

    const int cg  = threadIdx.x & 7;
    const int rg  = threadIdx.x >> 3;      // 0..31
    const int col = cg << 3;

    float acc[3][8];
    #pragma unroll
    for (int r = 0; r < 3; r++)
        #pragma unroll
        for (int j = 0; j < 8; j++) acc[r][j] = 0.f;

    #pragma unroll 4
    for (int k4 = 0; k4 < D; k4 += 4) {
        float xr[3][4];
        #pragma unroll
        for (int r = 0; r < 3; r++)
            *(float4*)xr[r] = *(const float4*)&Xs[(rg + 32 * r) * XSTRIDE + k4];
        #pragma unroll
        for (int kk = 0; kk < 4; kk++) {
            float4 w0 = *(const float4*)&Wt[(k4 + kk) * D + col];
            float4 w1 = *(const float4*)&Wt[(k4 + kk) * D + col + 4];
            float wv[8] = {w0.x, w0.y, w0.z, w0.w, w1.x, w1.y, w1.z, w1.w};
            #pragma unroll
            for (int r = 0; r < 3; r++) {
                float xv = xr[r][kk];
                #pragma unroll
                for (int j = 0; j < 8; j++)
                    acc[r][j] = fmaf(xv, wv[j], acc[r][j]);
            }
        }
    }

    #pragma unroll
    for (int r = 0; r < 3; r++) {
        int gi = base + rg + 32 * r;
        if (gi >= NN) continue;
        float s  = g_dis[gi];
        float ss = s * s;
        float4 h0 = make_float4(acc[r][0], acc[r][1], acc[r][2], acc[r][3]);
        float4 h1 = make_float4(acc[r][4], acc[r][5], acc[r][6], acc[r][7]);
        *(float4*)&g_h[gi * D + col]     = h0;
        *(float4*)&g_h[gi * D + col + 4] = h1;
        float4 o0 = make_float4(ss * h0.x, ss * h0.y, ss * h0.z, ss * h0.w);
        float4 o1 = make_float4(ss * h1.x, ss * h1.y, ss * h1.z, ss * h1.w);
        *(float4*)&out[gi * D + col]     = o0;
        *(float4*)&out[gi * D + col + 4] = o1;
    }
}

// ---------------------------------------------------------------------------
// Edge scatter: out[dst] += norm[e] * h[src].  16 threads per edge (float4 each).
__global__ __launch_bounds__(256) void k_msg(const int* __restrict__ src,
                                             const int* __restrict__ dst,
                                             float* __restrict__ out) {
    long long t = (long long)blockIdx.x * blockDim.x + threadIdx.x;
    int e = (int)(t >> 4);
    if (e >= NE) return;
    int c = (int)(t & 15) << 2;

    int r  = src[e];
    int cl = dst[e];
    float norm = g_norm[e];

    float4 hv = *(const float4*)&g_h[r * D + c];
    float4 m;
    m.x = norm * hv.x;
    m.y = norm * hv.y;
    m.z = norm * hv.z;
    m.w = norm * hv.w;

    float* p = &out[cl * D + c];
    asm volatile("red.global.add.v4.f32 [%0], {%1, %2, %3, %4};"
                 :: "l"(p), "f"(m.x), "f"(m.y), "f"(m.z), "f"(m.w)
                 : "memory");
}

// ---------------------------------------------------------------------------
__global__ void k_final(float* __restrict__ out, const float* __restrict__ b) {
    int t = blockIdx.x * blockDim.x + threadIdx.x;   // one float4 per thread
    if (t < NN * (D / 4)) {
        int c = (t & 15) << 2;
        float4 v = *(float4*)&out[t * 4];
        v.x = fmaxf(v.x + __ldg(&b[c + 0]), 0.f);
        v.y = fmaxf(v.y + __ldg(&b[c + 1]), 0.f);
        v.z = fmaxf(v.z + __ldg(&b[c + 2]), 0.f);
        v.w = fmaxf(v.w + __ldg(&b[c + 3]), 0.f);
        *(float4*)&out[t * 4] = v;
    }
}

// ---------------------------------------------------------------------------
extern "C" void kernel_launch(void* const* d_in, const int* in_sizes, int n_in,
                              void* d_out, int out_size) {
    const float* x  = (const float*)d_in[0];
    const int*   ei = (const int*)d_in[1];     // [2, NE] row-major
    const float* ea = (const float*)d_in[2];
    const float* W  = (const float*)d_in[3];
    const float* b  = (const float*)d_in[4];
    float* out = (float*)d_out;

    const int* src = ei;
    const int* dst = ei + NE;

    k_init_deg<<<(NN + 255) / 256, 256>>>();
    k_deg<<<(NE + 255) / 256, 256>>>(dst, ea);
    k_rsqrt<<<(NN + 255) / 256, 256>>>();
    k_norm<<<(NE + 255) / 256, 256>>>(src, dst, ea);
    k_gemm<<<(NN + GROWS - 1) / GROWS, 256>>>(x, W, out);
    {
        long long threads = (long long)NE * 16;
        int blocks = (int)((threads + 255) / 256);
        k_msg<<<blocks, 256>>>(src, dst, out);
    }
    k_final<<<(NN * (D / 4) + 255) / 256, 256>>>(out, b);
}